// round 8
// baseline (speedup 1.0000x reference)
#include <cuda_runtime.h>
#include <cuda_fp16.h>
#include <stdint.h>

// Problem dims
#define BB   64
#define TT   4096
#define NTOK (BB*TT)          // 262144
#define TOKPC 256             // tokens per CTA
#define NCTAS (NTOK/TOKPC)    // 1024

// smem strides (halves), conflict-free for LDSM (row stride in 16B units coprime with 8)
#define SC 104                // comb stride (K=96 padded)
#define SH 136                // weight stride (K=128 padded)

// ---------------- device scratch ----------------
__device__ __align__(16) __half g_wT[(size_t)BB * 64 * 64 * 64]; // [b][y][x][c] fp16, 32MB
__device__ __align__(16) __half g_wts[4 * 4 * 128 * 128];        // [net][layer][n][k] fp16
__device__ __align__(4) __half g_biasH[4 * 4 * 128];             // [net][layer][n] fp16
__device__ float g_part[2][NCTAS];                               // per-tile s-sums

// ---------------- helpers ----------------
__device__ __forceinline__ void mma16816(float c[4], const unsigned a0, const unsigned a1,
                                         const unsigned a2, const unsigned a3,
                                         unsigned b0, unsigned b1) {
    asm volatile(
        "mma.sync.aligned.m16n8k16.row.col.f32.f16.f16.f32 "
        "{%0,%1,%2,%3}, {%4,%5,%6,%7}, {%8,%9}, {%0,%1,%2,%3};"
        : "+f"(c[0]), "+f"(c[1]), "+f"(c[2]), "+f"(c[3])
        : "r"(a0), "r"(a1), "r"(a2), "r"(a3), "r"(b0), "r"(b1));
}

__device__ __forceinline__ void ldsm_x4(unsigned r[4], uint32_t addr) {
    asm volatile("ldmatrix.sync.aligned.m8n8.x4.shared.b16 {%0,%1,%2,%3}, [%4];"
                 : "=r"(r[0]), "=r"(r[1]), "=r"(r[2]), "=r"(r[3]) : "r"(addr));
}

__device__ __forceinline__ uint32_t smem_u32(const void* p) {
    uint32_t a;
    asm("{ .reg .u64 t; cvta.to.shared.u64 t, %1; cvt.u32.u64 %0, t; }" : "=r"(a) : "l"(p));
    return a;
}

// f32 silu, 1 MUFU: v * 0.5*(tanh(v/2)+1)
__device__ __forceinline__ float fast_silu(float v) {
    float t;
    asm("tanh.approx.f32 %0, %1;" : "=f"(t) : "f"(0.5f * v));
    return 0.5f * v * (t + 1.0f);
}
__device__ __forceinline__ unsigned packh2(float a, float b) {
    __half2 h = __floats2half2_rn(a, b);
    return *(unsigned*)&h;
}

// packed silu: per 2 values, 1 MUFU (t-net only)
__device__ __forceinline__ __half2 silu_h2(float c0, float c1, __half2 bias) {
    __half2 p = __hadd2(__floats2half2_rn(c0, c1), bias);
    __half2 u = __hmul2(p, __float2half2_rn(0.5f));
    __half2 t;
    asm("tanh.approx.f16x2 %0, %1;" : "=r"(*(unsigned*)&t) : "r"(*(unsigned*)&u));
    return __hfma2(u, t, u);
}

#define CP_ASYNC16(dst, src) \
    asm volatile("cp.async.cg.shared.global [%0], [%1], 16;" :: "r"(dst), "l"(src))
#define CP_COMMIT() asm volatile("cp.async.commit_group;" ::: "memory")

// ---------------- transpose w[B,C,H,W] f32 -> wT[b][y][x][c] fp16 ----------------
__global__ void k_transpose(const float* __restrict__ w) {
    __shared__ float tile[64][65];
    int bid = blockIdx.x;
    int b = bid >> 6, y = bid & 63;
    int t = threadIdx.x;
    {
        int c = t >> 2, xq = (t & 3) * 16;
        const float4* src = (const float4*)(w + ((((b << 6) | c) << 6 | y) << 6) + xq);
#pragma unroll
        for (int j = 0; j < 4; j++) {
            float4 v = src[j];
            tile[c][xq + 4 * j + 0] = v.x;
            tile[c][xq + 4 * j + 1] = v.y;
            tile[c][xq + 4 * j + 2] = v.z;
            tile[c][xq + 4 * j + 3] = v.w;
        }
    }
    __syncthreads();
    {
        int xx = t >> 2, cq = (t & 3) * 16;
        __half2* dst = (__half2*)(g_wT + ((((size_t)(((b << 6) | y)) << 6 | xx)) << 6) + cq);
#pragma unroll
        for (int j = 0; j < 8; j++)
            dst[j] = __floats2half2_rn(tile[cq + 2 * j][xx], tile[cq + 2 * j + 1][xx]);
    }
}

// ---------------- pack weights (permuted cols: [lf 0..63 | cond 64..79 | z 80 | 0]) ----------------
__global__ void k_pack(const float* __restrict__ W0, const float* __restrict__ b0,
                       const float* __restrict__ W1, const float* __restrict__ b1) {
    int idx = blockIdx.x * 256 + threadIdx.x;      // 262144 total
    int net = idx >> 16;
    int rem = idx & 65535;
    int layer = rem >> 14;
    int rem2 = rem & 16383;
    int n = rem2 >> 7, k = rem2 & 127;
    float v = 0.f;
    if (layer == 0) {
        int oc = -1;
        if (k < 64) oc = 1 + k;
        else if (k < 80) oc = 65 + (k - 64);
        else if (k == 80) oc = 0;
        if (oc >= 0) v = W0[(net * 128 + n) * 81 + oc];
    } else {
        v = W1[((net * 3 + (layer - 1)) * 128 + n) * 128 + k];
    }
    g_wts[idx] = __float2half_rn(v);
    if (idx < 2048) {
        int bn = idx >> 9, bl = (idx >> 7) & 3, bb_ = idx & 127;
        float bv = (bl == 0) ? b0[bn * 128 + bb_]
                             : b1[((bn * 3 + bl - 1) * 128) + bb_];
        g_biasH[idx] = __float2half_rn(bv);
    }
}

// ---------------- fused coupling pass: A-in-registers pipeline ----------------
template <int PASS>
__global__ void __launch_bounds__(256, 1) k_pass(
    const float* __restrict__ x, const float* __restrict__ cond,
    const float* __restrict__ W2, const float* __restrict__ b2,
    float* __restrict__ out) {
    extern __shared__ __align__(16) char smraw[];
    __half* combS  = (__half*)smraw;                          // 256 x SC
    __half* wbuf0  = (__half*)(smraw + 53248);                // 3 weight buffers 128 x SH
    __half* sbiasH = (__half*)(smraw + 157696);               // 8 x 128 halves (2KB)
    float*  w2s    = (float*)(smraw + 159744);                // 2 x 128
    float*  sraw   = (float*)(smraw + 160768);                // 256
    float*  traw   = (float*)(smraw + 161792);                // 256
    float*  sred   = (float*)(smraw + 162816);                // 256

    int tid = threadIdx.x;
    int wid = tid >> 5, lane = tid & 31;
    int gid = lane >> 2, tig = lane & 3;
    int tile = blockIdx.x;

    uint32_t combA = smem_u32(combS);
    uint32_t wbA[3] = {smem_u32(wbuf0), smem_u32(wbuf0 + 128 * SH),
                       smem_u32(wbuf0 + 2 * 128 * SH)};

    // stage biases (fp16) + w2 (contiguous per pass)
    {
        const unsigned* gb = (const unsigned*)(g_biasH + PASS * 1024);
        ((unsigned*)sbiasH)[tid]       = gb[tid];
        ((unsigned*)sbiasH)[tid + 256] = gb[tid + 256];
        w2s[tid] = __ldg(&W2[PASS * 256 + tid]);
    }

    // prologue weight prefetch: layers 0 and 1
    {
#pragma unroll
        for (int i = 0; i < 8; i++) {
            int ci = tid + i * 256;
            int n = ci >> 4, q = ci & 15;
            CP_ASYNC16(wbA[0] + (n * SH + q * 8) * 2,
                       (const char*)g_wts + ((size_t)(PASS * 8 + 0) << 15) + ci * 16);
        }
        CP_COMMIT();
#pragma unroll
        for (int i = 0; i < 8; i++) {
            int ci = tid + i * 256;
            int n = ci >> 4, q = ci & 15;
            CP_ASYNC16(wbA[1] + (n * SH + q * 8) * 2,
                       (const char*)g_wts + ((size_t)(PASS * 8 + 1) << 15) + ci * 16);
        }
        CP_COMMIT();
    }

    // ===== gather + build comb (one thread per token) =====
    {
        int g0 = tile * TOKPC + tid;
        int b = g0 >> 12;
        float zy = __ldg(&x[g0 * 2 + 1]);
        float zx = (PASS == 0) ? __ldg(&x[g0 * 2]) : out[g0 * 2];
        float zkeep = (PASS == 0) ? zy : zx;
        float ix = zx * 63.f, iy = zy * 63.f;
        float ix0 = floorf(ix), iy0 = floorf(iy);
        float wx1 = ix - ix0, wx0 = 1.f - wx1;
        float wy1 = iy - iy0, wy0 = 1.f - wy1;
        float acc[64];
#pragma unroll
        for (int i = 0; i < 64; i++) acc[i] = 0.f;
        float cxs[4] = {ix0, ix0 + 1.f, ix0, ix0 + 1.f};
        float cys[4] = {iy0, iy0, iy0 + 1.f, iy0 + 1.f};
        float cws[4] = {wy0 * wx0, wy0 * wx1, wy1 * wx0, wy1 * wx1};
#pragma unroll
        for (int cr = 0; cr < 4; cr++) {
            float xf = cxs[cr], yf = cys[cr], wt = cws[cr];
            if (xf >= 0.f && xf <= 63.f && yf >= 0.f && yf <= 63.f) {
                int xi = (int)xf, yi = (int)yf;
                const __half2* src = (const __half2*)(
                    g_wT + (((size_t)((b << 6) | yi) << 6 | xi) << 6));
#pragma unroll
                for (int j = 0; j < 32; j++) {
                    float2 f = __half22float2(src[j]);
                    acc[2 * j]     += wt * f.x;
                    acc[2 * j + 1] += wt * f.y;
                }
            }
        }
        __half* crow = combS + tid * SC;
        __half2* dst = (__half2*)crow;
#pragma unroll
        for (int j = 0; j < 32; j++) dst[j] = __floats2half2_rn(acc[2 * j], acc[2 * j + 1]);
#pragma unroll
        for (int i = 0; i < 16; i++)
            crow[64 + i] = __float2half_rn(__ldg(&cond[b * 16 + i]));
        crow[80] = __float2half_rn(zkeep);
#pragma unroll
        for (int cc = 81; cc < 96; cc++) crow[cc] = __float2half_rn(0.f);
    }

    // ldmatrix per-thread offsets
    int aRow = lane & 15;
    int aK   = (lane >> 4) * 8;
    int bRow = (lane & 7) + ((lane >> 4) & 1) * 8;
    int bK   = ((lane >> 3) & 1) * 8;

    unsigned aPack[2][16][2];   // half2-packed activations: [m-tile][n-tile][row/row+8]

    // ===== 8 layers (2 nets x 4), weights pipelined via cp.async =====
    for (int li = 0; li < 8; li++) {
        if (li < 7) asm volatile("cp.async.wait_group 1;" ::: "memory");
        else        asm volatile("cp.async.wait_group 0;" ::: "memory");
        __syncthreads();

        // prefetch layer li+2 into buf[(li+2)%3]
        if (li + 2 < 8) {
            uint32_t dstA = wbA[(li + 2) % 3];
            const char* srcp = (const char*)g_wts + ((size_t)(PASS * 8 + li + 2) << 15);
#pragma unroll
            for (int i = 0; i < 8; i++) {
                int ci = tid + i * 256;
                int n = ci >> 4, q = ci & 15;
                CP_ASYNC16(dstA + (n * SH + q * 8) * 2, srcp + ci * 16);
            }
            CP_COMMIT();
        }

        uint32_t wA = wbA[li % 3];
        uint32_t bb = wA + (bRow * SH + bK) * 2;
        int layer = li & 3;

        float acc[2][16][4];
#pragma unroll
        for (int mt = 0; mt < 2; mt++)
#pragma unroll
            for (int nt = 0; nt < 16; nt++)
#pragma unroll
                for (int q = 0; q < 4; q++) acc[mt][nt][q] = 0.f;

        if (layer == 0) {
            // A from comb via LDSM, K=96 (6 ksteps)
            uint32_t a0 = combA + ((wid * 32 + aRow) * SC + aK) * 2;
            uint32_t a1 = combA + ((wid * 32 + 16 + aRow) * SC + aK) * 2;
#pragma unroll
            for (int ks = 0; ks < 6; ks++) {
                unsigned af0[4], af1[4];
                ldsm_x4(af0, a0 + ks * 32);
                ldsm_x4(af1, a1 + ks * 32);
#pragma unroll
                for (int ntp = 0; ntp < 8; ntp++) {
                    unsigned bf[4];
                    ldsm_x4(bf, bb + (ntp * 16 * SH) * 2 + ks * 32);
                    mma16816(acc[0][2 * ntp],     af0[0], af0[1], af0[2], af0[3], bf[0], bf[1]);
                    mma16816(acc[0][2 * ntp + 1], af0[0], af0[1], af0[2], af0[3], bf[2], bf[3]);
                    mma16816(acc[1][2 * ntp],     af1[0], af1[1], af1[2], af1[3], bf[0], bf[1]);
                    mma16816(acc[1][2 * ntp + 1], af1[0], af1[1], af1[2], af1[3], bf[2], bf[3]);
                }
            }
        } else {
            // A from registers (aPack), K=128 (8 ksteps)
#pragma unroll
            for (int ks = 0; ks < 8; ks++) {
#pragma unroll
                for (int ntp = 0; ntp < 8; ntp++) {
                    unsigned bf[4];
                    ldsm_x4(bf, bb + (ntp * 16 * SH) * 2 + ks * 32);
                    mma16816(acc[0][2 * ntp], aPack[0][2 * ks][0], aPack[0][2 * ks][1],
                             aPack[0][2 * ks + 1][0], aPack[0][2 * ks + 1][1], bf[0], bf[1]);
                    mma16816(acc[0][2 * ntp + 1], aPack[0][2 * ks][0], aPack[0][2 * ks][1],
                             aPack[0][2 * ks + 1][0], aPack[0][2 * ks + 1][1], bf[2], bf[3]);
                    mma16816(acc[1][2 * ntp], aPack[1][2 * ks][0], aPack[1][2 * ks][1],
                             aPack[1][2 * ks + 1][0], aPack[1][2 * ks + 1][1], bf[0], bf[1]);
                    mma16816(acc[1][2 * ntp + 1], aPack[1][2 * ks][0], aPack[1][2 * ks][1],
                             aPack[1][2 * ks + 1][0], aPack[1][2 * ks + 1][1], bf[2], bf[3]);
                }
            }
        }

        const __half* lbH = sbiasH + li * 128;
        if (li < 3) {
            // s-net interior: fp32 silu (precision-critical path feeds log_det)
#pragma unroll
            for (int mt = 0; mt < 2; mt++)
#pragma unroll
                for (int nt = 0; nt < 16; nt++) {
                    int c = nt * 8 + tig * 2;
                    float2 bf2 = __half22float2(*(const __half2*)(lbH + c));
                    float v0 = fast_silu(acc[mt][nt][0] + bf2.x);
                    float v1 = fast_silu(acc[mt][nt][1] + bf2.y);
                    float v2 = fast_silu(acc[mt][nt][2] + bf2.x);
                    float v3 = fast_silu(acc[mt][nt][3] + bf2.y);
                    aPack[mt][nt][0] = packh2(v0, v1);
                    aPack[mt][nt][1] = packh2(v2, v3);
                }
        } else if (li == 3) {
            // s-net final GEMV: fp32 silu + fp32 dot
            const float* w2 = w2s;
#pragma unroll
            for (int mt = 0; mt < 2; mt++) {
                float p0 = 0.f, p1 = 0.f;
#pragma unroll
                for (int nt = 0; nt < 16; nt++) {
                    int c = nt * 8 + tig * 2;
                    float2 bf2 = __half22float2(*(const __half2*)(lbH + c));
                    float w0 = w2[c], w1 = w2[c + 1];
                    p0 += fast_silu(acc[mt][nt][0] + bf2.x) * w0
                        + fast_silu(acc[mt][nt][1] + bf2.y) * w1;
                    p1 += fast_silu(acc[mt][nt][2] + bf2.x) * w0
                        + fast_silu(acc[mt][nt][3] + bf2.y) * w1;
                }
                p0 += __shfl_xor_sync(0xffffffffu, p0, 1);
                p0 += __shfl_xor_sync(0xffffffffu, p0, 2);
                p1 += __shfl_xor_sync(0xffffffffu, p1, 1);
                p1 += __shfl_xor_sync(0xffffffffu, p1, 2);
                if (tig == 0) {
                    sraw[wid * 32 + mt * 16 + gid]     = p0;
                    sraw[wid * 32 + mt * 16 + gid + 8] = p1;
                }
            }
        } else if (li < 7) {
            // t-net interior: packed f16x2 silu (z-path has 60x error margin)
#pragma unroll
            for (int mt = 0; mt < 2; mt++)
#pragma unroll
                for (int nt = 0; nt < 16; nt++) {
                    int c = nt * 8 + tig * 2;
                    __half2 bias = *(const __half2*)(lbH + c);
                    __half2 r0 = silu_h2(acc[mt][nt][0], acc[mt][nt][1], bias);
                    __half2 r1 = silu_h2(acc[mt][nt][2], acc[mt][nt][3], bias);
                    aPack[mt][nt][0] = *(unsigned*)&r0;
                    aPack[mt][nt][1] = *(unsigned*)&r1;
                }
        } else {
            // t-net final GEMV: packed silu then f32 dot
            const float* w2 = w2s + 128;
#pragma unroll
            for (int mt = 0; mt < 2; mt++) {
                float p0 = 0.f, p1 = 0.f;
#pragma unroll
                for (int nt = 0; nt < 16; nt++) {
                    int c = nt * 8 + tig * 2;
                    __half2 bias = *(const __half2*)(lbH + c);
                    float w0 = w2[c], w1 = w2[c + 1];
                    float2 f0 = __half22float2(silu_h2(acc[mt][nt][0], acc[mt][nt][1], bias));
                    float2 f1 = __half22float2(silu_h2(acc[mt][nt][2], acc[mt][nt][3], bias));
                    p0 += f0.x * w0 + f0.y * w1;
                    p1 += f1.x * w0 + f1.y * w1;
                }
                p0 += __shfl_xor_sync(0xffffffffu, p0, 1);
                p0 += __shfl_xor_sync(0xffffffffu, p0, 2);
                p1 += __shfl_xor_sync(0xffffffffu, p1, 1);
                p1 += __shfl_xor_sync(0xffffffffu, p1, 2);
                if (tig == 0) {
                    traw[wid * 32 + mt * 16 + gid]     = p0;
                    traw[wid * 32 + mt * 16 + gid + 8] = p1;
                }
            }
        }
    }
    __syncthreads();

    // ===== coupling epilogue + deterministic block reduce of s =====
    {
        int g0 = tile * TOKPC + tid;
        float zold = (PASS == 0) ? __ldg(&x[g0 * 2]) : __ldg(&x[g0 * 2 + 1]);
        float sv = tanhf(sraw[tid] + __ldg(&b2[PASS * 2])) * 1.5f;
        float tv = traw[tid] + __ldg(&b2[PASS * 2 + 1]);
        float z = zold * __expf(sv) + tv;
        out[g0 * 2 + PASS] = z;
        sred[tid] = sv;
    }
    __syncthreads();
    if (tid < 128) sred[tid] += sred[tid + 128];
    __syncthreads();
    if (tid < 64) sred[tid] += sred[tid + 64];
    __syncthreads();
    if (tid < 32) {
        float v = sred[tid] + sred[tid + 32];
#pragma unroll
        for (int off = 16; off; off >>= 1) v += __shfl_xor_sync(0xffffffffu, v, off);
        if (tid == 0) g_part[PASS][tile] = v;
    }
}

// ---------------- log-det reduce ----------------
__global__ void k_reduce(float* __restrict__ out) {
    int b = threadIdx.x;
    if (b < BB) {
        float acc = 0.f;
        for (int i = 0; i < 16; i++)
            acc += g_part[0][b * 16 + i] + g_part[1][b * 16 + i];
        out[(size_t)NTOK * 2 + b] = acc;
    }
}

// ---------------- launcher ----------------
extern "C" void kernel_launch(void* const* d_in, const int* in_sizes, int n_in,
                              void* d_out, int out_size) {
    const float* x    = (const float*)d_in[0];
    const float* w    = (const float*)d_in[1];
    const float* cond = (const float*)d_in[2];
    const float* W0   = (const float*)d_in[3];
    const float* b0   = (const float*)d_in[4];
    const float* W1   = (const float*)d_in[5];
    const float* b1   = (const float*)d_in[6];
    const float* W2   = (const float*)d_in[7];
    const float* b2   = (const float*)d_in[8];
    float* out = (float*)d_out;

    const int SMEM = 163840;
    cudaFuncSetAttribute(k_pass<0>, cudaFuncAttributeMaxDynamicSharedMemorySize, SMEM);
    cudaFuncSetAttribute(k_pass<1>, cudaFuncAttributeMaxDynamicSharedMemorySize, SMEM);

    k_transpose<<<4096, 256>>>(w);
    k_pack<<<1024, 256>>>(W0, b0, W1, b1);
    k_pass<0><<<NCTAS, 256, SMEM>>>(x, cond, W2, b2, out);
    k_pass<1><<<NCTAS, 256, SMEM>>>(x, cond, W2, b2, out);
    k_reduce<<<1, 64>>>(out);
}

// round 9
// speedup vs baseline: 1.0718x; 1.0718x over previous
#include <cuda_runtime.h>
#include <cuda_fp16.h>
#include <stdint.h>

// Problem dims
#define BB   64
#define TT   4096
#define NTOK (BB*TT)          // 262144
#define TOKPC 256             // tokens per CTA
#define NCTAS (NTOK/TOKPC)    // 1024
#define NTHREADS 512

// smem strides (halves): row stride in 16B units coprime with 8 -> LDSM conflict-free
#define SC  104               // comb stride (K=96 padded)
#define SH  136               // weight stride (K=128 padded)
#define SHE 136               // hidden-exchange stride

// smem byte offsets
#define OFF_COMB   0
#define OFF_HEX    53248              // 256*SC*2
#define OFF_WB0    122880             // +256*SHE*2
#define OFF_WB1    157696             // +128*SH*2
#define OFF_BIAS   192512             // +128*SH*2
#define OFF_W2     194560             // +8*128*2
#define OFF_SPARTS 195584             // +256*4
#define OFF_SPARTT 197632             // +512*4
#define OFF_SRED   199680             // +512*4
#define SMEM_TOT   200704             // +256*4

// ---------------- device scratch ----------------
__device__ __align__(16) __half g_wT[(size_t)BB * 64 * 64 * 64]; // [b][y][x][c] fp16, 32MB
__device__ __align__(16) __half g_wts[4 * 4 * 128 * 128];        // [net][layer][n][k] fp16
__device__ __align__(4) __half g_biasH[4 * 4 * 128];             // [net][layer][n] fp16
__device__ float g_part[2][NCTAS];                               // per-tile s-sums

// ---------------- helpers ----------------
__device__ __forceinline__ void mma16816(float c[4], const unsigned a0, const unsigned a1,
                                         const unsigned a2, const unsigned a3,
                                         unsigned b0, unsigned b1) {
    asm volatile(
        "mma.sync.aligned.m16n8k16.row.col.f32.f16.f16.f32 "
        "{%0,%1,%2,%3}, {%4,%5,%6,%7}, {%8,%9}, {%0,%1,%2,%3};"
        : "+f"(c[0]), "+f"(c[1]), "+f"(c[2]), "+f"(c[3])
        : "r"(a0), "r"(a1), "r"(a2), "r"(a3), "r"(b0), "r"(b1));
}

__device__ __forceinline__ void ldsm_x4(unsigned r[4], uint32_t addr) {
    asm volatile("ldmatrix.sync.aligned.m8n8.x4.shared.b16 {%0,%1,%2,%3}, [%4];"
                 : "=r"(r[0]), "=r"(r[1]), "=r"(r[2]), "=r"(r[3]) : "r"(addr));
}

__device__ __forceinline__ uint32_t smem_u32(const void* p) {
    uint32_t a;
    asm("{ .reg .u64 t; cvta.to.shared.u64 t, %1; cvt.u32.u64 %0, t; }" : "=r"(a) : "l"(p));
    return a;
}

__device__ __forceinline__ float fast_silu(float v) {
    float t;
    asm("tanh.approx.f32 %0, %1;" : "=f"(t) : "f"(0.5f * v));
    return 0.5f * v * (t + 1.0f);
}
__device__ __forceinline__ unsigned packh2(float a, float b) {
    __half2 h = __floats2half2_rn(a, b);
    return *(unsigned*)&h;
}
__device__ __forceinline__ __half2 silu_h2(float c0, float c1, __half2 bias) {
    __half2 p = __hadd2(__floats2half2_rn(c0, c1), bias);
    __half2 u = __hmul2(p, __float2half2_rn(0.5f));
    __half2 t;
    asm("tanh.approx.f16x2 %0, %1;" : "=r"(*(unsigned*)&t) : "r"(*(unsigned*)&u));
    return __hfma2(u, t, u);
}

#define CP_ASYNC16(dst, src) \
    asm volatile("cp.async.cg.shared.global [%0], [%1], 16;" :: "r"(dst), "l"(src))
#define CP_COMMIT() asm volatile("cp.async.commit_group;" ::: "memory")

// ---------------- transpose w[B,C,H,W] f32 -> wT[b][y][x][c] fp16 ----------------
__global__ void k_transpose(const float* __restrict__ w) {
    __shared__ float tile[64][65];
    int bid = blockIdx.x;
    int b = bid >> 6, y = bid & 63;
    int t = threadIdx.x;
    {
        int c = t >> 2, xq = (t & 3) * 16;
        const float4* src = (const float4*)(w + ((((b << 6) | c) << 6 | y) << 6) + xq);
#pragma unroll
        for (int j = 0; j < 4; j++) {
            float4 v = src[j];
            tile[c][xq + 4 * j + 0] = v.x;
            tile[c][xq + 4 * j + 1] = v.y;
            tile[c][xq + 4 * j + 2] = v.z;
            tile[c][xq + 4 * j + 3] = v.w;
        }
    }
    __syncthreads();
    {
        int xx = t >> 2, cq = (t & 3) * 16;
        __half2* dst = (__half2*)(g_wT + ((((size_t)(((b << 6) | y)) << 6 | xx)) << 6) + cq);
#pragma unroll
        for (int j = 0; j < 8; j++)
            dst[j] = __floats2half2_rn(tile[cq + 2 * j][xx], tile[cq + 2 * j + 1][xx]);
    }
}

// ---------------- pack weights (permuted cols: [lf 0..63 | cond 64..79 | z 80 | 0]) ----------------
__global__ void k_pack(const float* __restrict__ W0, const float* __restrict__ b0,
                       const float* __restrict__ W1, const float* __restrict__ b1) {
    int idx = blockIdx.x * 256 + threadIdx.x;
    int net = idx >> 16;
    int rem = idx & 65535;
    int layer = rem >> 14;
    int rem2 = rem & 16383;
    int n = rem2 >> 7, k = rem2 & 127;
    float v = 0.f;
    if (layer == 0) {
        int oc = -1;
        if (k < 64) oc = 1 + k;
        else if (k < 80) oc = 65 + (k - 64);
        else if (k == 80) oc = 0;
        if (oc >= 0) v = W0[(net * 128 + n) * 81 + oc];
    } else {
        v = W1[((net * 3 + (layer - 1)) * 128 + n) * 128 + k];
    }
    g_wts[idx] = __float2half_rn(v);
    if (idx < 2048) {
        int bn = idx >> 9, bl = (idx >> 7) & 3, bb_ = idx & 127;
        float bv = (bl == 0) ? b0[bn * 128 + bb_]
                             : b1[((bn * 3 + bl - 1) * 128) + bb_];
        g_biasH[idx] = __float2half_rn(bv);
    }
}

// ---------------- fused coupling pass: hybrid reg/smem activations, 16 warps ----------------
template <int PASS>
__global__ void __launch_bounds__(NTHREADS, 1) k_pass(
    const float* __restrict__ x, const float* __restrict__ cond,
    const float* __restrict__ W2, const float* __restrict__ b2,
    float* __restrict__ out) {
    extern __shared__ __align__(16) char smraw[];
    __half* combS  = (__half*)(smraw + OFF_COMB);
    __half* hExS   = (__half*)(smraw + OFF_HEX);
    __half* sbiasH = (__half*)(smraw + OFF_BIAS);
    float*  w2s    = (float*)(smraw + OFF_W2);
    float*  spartS = (float*)(smraw + OFF_SPARTS);
    float*  spartT = (float*)(smraw + OFF_SPARTT);
    float*  sred   = (float*)(smraw + OFF_SRED);

    int tid = threadIdx.x;
    int wid = tid >> 5, lane = tid & 31;
    int gid = lane >> 2, tig = lane & 3;
    int rowg = wid & 7;          // 8 row-groups x 32 tokens
    int colg = wid >> 3;         // 2 col-groups x 64 cols
    int tile = blockIdx.x;

    uint32_t combA = smem_u32(combS);
    uint32_t hExA  = smem_u32(hExS);
    uint32_t wbA[2] = {smem_u32(smraw + OFF_WB0), smem_u32(smraw + OFF_WB1)};

    // stage biases (fp16, 1024 halves via 512 u32) + w2
    ((unsigned*)sbiasH)[tid] = ((const unsigned*)(g_biasH + PASS * 1024))[tid];
    if (tid < 256) w2s[tid] = __ldg(&W2[PASS * 256 + tid]);

    // prologue: prefetch layer 0 weights
    {
#pragma unroll
        for (int i = 0; i < 4; i++) {
            int ci = tid + i * 512;
            int n = ci >> 4, q = ci & 15;
            CP_ASYNC16(wbA[0] + (n * SH + q * 8) * 2,
                       (const char*)g_wts + ((size_t)(PASS * 8) << 15) + ci * 16);
        }
        CP_COMMIT();
    }

    // ===== gather + build comb (2 threads per token) =====
    {
        int tk = tid >> 1, p = tid & 1;
        int g0 = tile * TOKPC + tk;
        int b = g0 >> 12;
        float zy = __ldg(&x[g0 * 2 + 1]);
        float zx = (PASS == 0) ? __ldg(&x[g0 * 2]) : out[g0 * 2];
        float zkeep = (PASS == 0) ? zy : zx;
        float ix = zx * 63.f, iy = zy * 63.f;
        float ix0 = floorf(ix), iy0 = floorf(iy);
        float wx1 = ix - ix0, wx0 = 1.f - wx1;
        float wy1 = iy - iy0, wy0 = 1.f - wy1;
        float acc[32];
#pragma unroll
        for (int i = 0; i < 32; i++) acc[i] = 0.f;
        float cxs[4] = {ix0, ix0 + 1.f, ix0, ix0 + 1.f};
        float cys[4] = {iy0, iy0, iy0 + 1.f, iy0 + 1.f};
        float cws[4] = {wy0 * wx0, wy0 * wx1, wy1 * wx0, wy1 * wx1};
#pragma unroll
        for (int cr = 0; cr < 4; cr++) {
            float xf = cxs[cr], yf = cys[cr], wt = cws[cr];
            if (xf >= 0.f && xf <= 63.f && yf >= 0.f && yf <= 63.f) {
                int xi = (int)xf, yi = (int)yf;
                const __half2* src = (const __half2*)(
                    g_wT + ((((size_t)((b << 6) | yi) << 6 | xi)) << 6) + (p << 5));
#pragma unroll
                for (int j = 0; j < 16; j++) {
                    float2 f = __half22float2(src[j]);
                    acc[2 * j]     += wt * f.x;
                    acc[2 * j + 1] += wt * f.y;
                }
            }
        }
        __half* crow = combS + tk * SC;
        __half2* dst = (__half2*)(crow + p * 32);
#pragma unroll
        for (int j = 0; j < 16; j++) dst[j] = __floats2half2_rn(acc[2 * j], acc[2 * j + 1]);
        if (p == 0) {
#pragma unroll
            for (int i = 0; i < 16; i++)
                crow[64 + i] = __float2half_rn(__ldg(&cond[b * 16 + i]));
            crow[80] = __float2half_rn(zkeep);
#pragma unroll
            for (int cc = 81; cc < 88; cc++) crow[cc] = __float2half_rn(0.f);
        } else {
#pragma unroll
            for (int cc = 88; cc < 96; cc++) crow[cc] = __float2half_rn(0.f);
        }
    }

    // ldmatrix per-thread offsets
    int aRow = lane & 15;
    int aK   = (lane >> 4) * 8;
    int bRow = (lane & 7) + ((lane >> 4) & 1) * 8;
    int bK   = ((lane >> 3) & 1) * 8;

    unsigned aPack[2][8][2];   // own k-half activations in a-frag form

    // ===== 8 layers, weights double-buffered via cp.async =====
    for (int li = 0; li < 8; li++) {
        asm volatile("cp.async.wait_group 0;" ::: "memory");
        __syncthreads();

        // distance-1 prefetch of next layer into the other buffer
        if (li < 7) {
            uint32_t dstA = wbA[(li + 1) & 1];
            const char* srcp = (const char*)g_wts + ((size_t)(PASS * 8 + li + 1) << 15);
#pragma unroll
            for (int i = 0; i < 4; i++) {
                int ci = tid + i * 512;
                int n = ci >> 4, q = ci & 15;
                CP_ASYNC16(dstA + (n * SH + q * 8) * 2, srcp + ci * 16);
            }
            CP_COMMIT();
        }

        uint32_t wA = wbA[li & 1];
        uint32_t bb = wA + ((64 * colg + bRow) * SH + bK) * 2;

        float acc[2][8][4];
#pragma unroll
        for (int mt = 0; mt < 2; mt++)
#pragma unroll
            for (int nt = 0; nt < 8; nt++)
#pragma unroll
                for (int q = 0; q < 4; q++) acc[mt][nt][q] = 0.f;

        if (li == 0 || li == 4) {
            // A from comb (K=96, 6 ksteps)
            uint32_t a0 = combA + ((32 * rowg + aRow) * SC + aK) * 2;
            uint32_t a1 = a0 + 16 * SC * 2;
#pragma unroll
            for (int ks = 0; ks < 6; ks++) {
                unsigned af0[4], af1[4];
                ldsm_x4(af0, a0 + ks * 32);
                ldsm_x4(af1, a1 + ks * 32);
#pragma unroll
                for (int ntp = 0; ntp < 4; ntp++) {
                    unsigned bf[4];
                    ldsm_x4(bf, bb + (ntp * 16 * SH) * 2 + ks * 32);
                    mma16816(acc[0][2 * ntp],     af0[0], af0[1], af0[2], af0[3], bf[0], bf[1]);
                    mma16816(acc[0][2 * ntp + 1], af0[0], af0[1], af0[2], af0[3], bf[2], bf[3]);
                    mma16816(acc[1][2 * ntp],     af1[0], af1[1], af1[2], af1[3], bf[0], bf[1]);
                    mma16816(acc[1][2 * ntp + 1], af1[0], af1[1], af1[2], af1[3], bf[2], bf[3]);
                }
            }
        } else {
            // partner k-half from hEx (4 ksteps)
            int pc = colg ^ 1;
            uint32_t pbase = hExA + ((32 * rowg + aRow) * SHE + 64 * pc + aK) * 2;
            int pks0 = 4 * pc, oks0 = 4 * colg;
#pragma unroll
            for (int l = 0; l < 4; l++) {
                unsigned af0[4], af1[4];
                ldsm_x4(af0, pbase + l * 32);
                ldsm_x4(af1, pbase + 16 * SHE * 2 + l * 32);
#pragma unroll
                for (int ntp = 0; ntp < 4; ntp++) {
                    unsigned bf[4];
                    ldsm_x4(bf, bb + (ntp * 16 * SH) * 2 + (pks0 + l) * 32);
                    mma16816(acc[0][2 * ntp],     af0[0], af0[1], af0[2], af0[3], bf[0], bf[1]);
                    mma16816(acc[0][2 * ntp + 1], af0[0], af0[1], af0[2], af0[3], bf[2], bf[3]);
                    mma16816(acc[1][2 * ntp],     af1[0], af1[1], af1[2], af1[3], bf[0], bf[1]);
                    mma16816(acc[1][2 * ntp + 1], af1[0], af1[1], af1[2], af1[3], bf[2], bf[3]);
                }
            }
            // own k-half from registers (4 ksteps)
#pragma unroll
            for (int l = 0; l < 4; l++) {
#pragma unroll
                for (int ntp = 0; ntp < 4; ntp++) {
                    unsigned bf[4];
                    ldsm_x4(bf, bb + (ntp * 16 * SH) * 2 + (oks0 + l) * 32);
                    mma16816(acc[0][2 * ntp], aPack[0][2 * l][0], aPack[0][2 * l][1],
                             aPack[0][2 * l + 1][0], aPack[0][2 * l + 1][1], bf[0], bf[1]);
                    mma16816(acc[0][2 * ntp + 1], aPack[0][2 * l][0], aPack[0][2 * l][1],
                             aPack[0][2 * l + 1][0], aPack[0][2 * l + 1][1], bf[2], bf[3]);
                    mma16816(acc[1][2 * ntp], aPack[1][2 * l][0], aPack[1][2 * l][1],
                             aPack[1][2 * l + 1][0], aPack[1][2 * l + 1][1], bf[0], bf[1]);
                    mma16816(acc[1][2 * ntp + 1], aPack[1][2 * l][0], aPack[1][2 * l][1],
                             aPack[1][2 * l + 1][0], aPack[1][2 * l + 1][1], bf[2], bf[3]);
                }
            }
        }

        // hEx rewrite hazard: only when this layer read hEx and next write goes there
        if (li == 1 || li == 2 || li == 5 || li == 6) __syncthreads();

        const __half* lbH = sbiasH + li * 128 + 64 * colg;
        if (li == 3 || li == 7) {
            // final GEMV of this net over our 64 cols
            float* sp = (li == 3) ? spartS : spartT;
            const float* w2 = w2s + (li >> 2) * 128 + 64 * colg;
#pragma unroll
            for (int mt = 0; mt < 2; mt++) {
                float p0 = 0.f, p1 = 0.f;
                if (li == 3) {
#pragma unroll
                    for (int nt = 0; nt < 8; nt++) {
                        int c = nt * 8 + tig * 2;
                        float2 bf2 = __half22float2(*(const __half2*)(lbH + c));
                        float w0 = w2[c], w1 = w2[c + 1];
                        p0 += fast_silu(acc[mt][nt][0] + bf2.x) * w0
                            + fast_silu(acc[mt][nt][1] + bf2.y) * w1;
                        p1 += fast_silu(acc[mt][nt][2] + bf2.x) * w0
                            + fast_silu(acc[mt][nt][3] + bf2.y) * w1;
                    }
                } else {
#pragma unroll
                    for (int nt = 0; nt < 8; nt++) {
                        int c = nt * 8 + tig * 2;
                        __half2 bias = *(const __half2*)(lbH + c);
                        float w0 = w2[c], w1 = w2[c + 1];
                        float2 f0 = __half22float2(silu_h2(acc[mt][nt][0], acc[mt][nt][1], bias));
                        float2 f1 = __half22float2(silu_h2(acc[mt][nt][2], acc[mt][nt][3], bias));
                        p0 += f0.x * w0 + f0.y * w1;
                        p1 += f1.x * w0 + f1.y * w1;
                    }
                }
                p0 += __shfl_xor_sync(0xffffffffu, p0, 1);
                p0 += __shfl_xor_sync(0xffffffffu, p0, 2);
                p1 += __shfl_xor_sync(0xffffffffu, p1, 1);
                p1 += __shfl_xor_sync(0xffffffffu, p1, 2);
                if (tig == 0) {
                    sp[colg * 256 + 32 * rowg + 16 * mt + gid]     = p0;
                    sp[colg * 256 + 32 * rowg + 16 * mt + gid + 8] = p1;
                }
            }
        } else {
            // interior epilogue: silu -> aPack (own half) + hEx (for partner)
#pragma unroll
            for (int mt = 0; mt < 2; mt++) {
                __half* exb = hExS + (32 * rowg + 16 * mt + gid) * SHE + 64 * colg + tig * 2;
#pragma unroll
                for (int nt = 0; nt < 8; nt++) {
                    unsigned r0, r1;
                    if (li < 3) {
                        float2 bf2 = __half22float2(*(const __half2*)(lbH + nt * 8 + tig * 2));
                        r0 = packh2(fast_silu(acc[mt][nt][0] + bf2.x),
                                    fast_silu(acc[mt][nt][1] + bf2.y));
                        r1 = packh2(fast_silu(acc[mt][nt][2] + bf2.x),
                                    fast_silu(acc[mt][nt][3] + bf2.y));
                    } else {
                        __half2 bias = *(const __half2*)(lbH + nt * 8 + tig * 2);
                        __half2 h0 = silu_h2(acc[mt][nt][0], acc[mt][nt][1], bias);
                        __half2 h1 = silu_h2(acc[mt][nt][2], acc[mt][nt][3], bias);
                        r0 = *(unsigned*)&h0;
                        r1 = *(unsigned*)&h1;
                    }
                    aPack[mt][nt][0] = r0;
                    aPack[mt][nt][1] = r1;
                    *(unsigned*)(exb + nt * 8)            = r0;
                    *(unsigned*)(exb + 8 * SHE + nt * 8)  = r1;
                }
            }
        }
    }
    __syncthreads();

    // ===== coupling epilogue + deterministic block reduce of s =====
    if (tid < 256) {
        int g0 = tile * TOKPC + tid;
        float zold = (PASS == 0) ? __ldg(&x[g0 * 2]) : __ldg(&x[g0 * 2 + 1]);
        float s_lin = spartS[tid] + spartS[256 + tid] + __ldg(&b2[PASS * 2]);
        float t_lin = spartT[tid] + spartT[256 + tid] + __ldg(&b2[PASS * 2 + 1]);
        float sv = tanhf(s_lin) * 1.5f;
        out[g0 * 2 + PASS] = zold * __expf(sv) + t_lin;
        sred[tid] = sv;
    }
    __syncthreads();
    if (tid < 128) sred[tid] += sred[tid + 128];
    __syncthreads();
    if (tid < 64) sred[tid] += sred[tid + 64];
    __syncthreads();
    if (tid < 32) {
        float v = sred[tid] + sred[tid + 32];
#pragma unroll
        for (int off = 16; off; off >>= 1) v += __shfl_xor_sync(0xffffffffu, v, off);
        if (tid == 0) g_part[PASS][tile] = v;
    }
}

// ---------------- log-det reduce ----------------
__global__ void k_reduce(float* __restrict__ out) {
    int b = threadIdx.x;
    if (b < BB) {
        float acc = 0.f;
        for (int i = 0; i < 16; i++)
            acc += g_part[0][b * 16 + i] + g_part[1][b * 16 + i];
        out[(size_t)NTOK * 2 + b] = acc;
    }
}

// ---------------- launcher ----------------
extern "C" void kernel_launch(void* const* d_in, const int* in_sizes, int n_in,
                              void* d_out, int out_size) {
    const float* x    = (const float*)d_in[0];
    const float* w    = (const float*)d_in[1];
    const float* cond = (const float*)d_in[2];
    const float* W0   = (const float*)d_in[3];
    const float* b0   = (const float*)d_in[4];
    const float* W1   = (const float*)d_in[5];
    const float* b1   = (const float*)d_in[6];
    const float* W2   = (const float*)d_in[7];
    const float* b2   = (const float*)d_in[8];
    float* out = (float*)d_out;

    cudaFuncSetAttribute(k_pass<0>, cudaFuncAttributeMaxDynamicSharedMemorySize, SMEM_TOT);
    cudaFuncSetAttribute(k_pass<1>, cudaFuncAttributeMaxDynamicSharedMemorySize, SMEM_TOT);

    k_transpose<<<4096, 256>>>(w);
    k_pack<<<1024, 256>>>(W0, b0, W1, b1);
    k_pass<0><<<NCTAS, NTHREADS, SMEM_TOT>>>(x, cond, W2, b2, out);
    k_pass<1><<<NCTAS, NTHREADS, SMEM_TOT>>>(x, cond, W2, b2, out);
    k_reduce<<<1, 64>>>(out);
}

// round 10
// speedup vs baseline: 1.1422x; 1.0656x over previous
#include <cuda_runtime.h>
#include <cuda_fp16.h>
#include <stdint.h>

// Problem dims
#define BB   64
#define TT   4096
#define NTOK (BB*TT)          // 262144
#define TOKPC 128             // tokens per CTA
#define NCTAS (NTOK/TOKPC)    // 2048
#define NTHREADS 256

// smem strides (halves): row stride in 16B units coprime with 8 -> LDSM conflict-free
#define SC  104               // comb stride (K=96 padded)
#define SH  136               // weight stride (K=128 padded)
#define SHE 136               // hidden-exchange stride

// smem byte offsets
#define OFF_COMB   0                  // 128*SC*2      = 26624
#define OFF_HEX    26624              // 128*SHE*2     = 34816
#define OFF_WB     61440              // 128*SH*2      = 34816
#define OFF_BIAS   96256              // 2048 halves   = 4096
#define OFF_W2     100352             // 512 floats    = 2048
#define OFF_SPS    102400             // 256 floats    = 1024
#define OFF_SPT    103424             // 256 floats    = 1024
#define OFF_ZA     104448             // 128 floats    = 512
#define OFF_SRED   104960             // 128 floats    = 512
#define SMEM_TOT   105472

// ---------------- device scratch ----------------
__device__ __align__(16) __half g_wT[(size_t)BB * 64 * 64 * 64]; // [b][y][x][c] fp16, 32MB
__device__ __align__(16) __half g_wts[4 * 4 * 128 * 128];        // [net][layer][n][k] fp16
__device__ __align__(4) __half g_biasH[4 * 4 * 128];             // [net][layer][n] fp16
__device__ float g_part[NCTAS];                                  // per-tile s-sums (both passes)

// ---------------- helpers ----------------
__device__ __forceinline__ void mma16816(float c[4], const unsigned a0, const unsigned a1,
                                         const unsigned a2, const unsigned a3,
                                         unsigned b0, unsigned b1) {
    asm volatile(
        "mma.sync.aligned.m16n8k16.row.col.f32.f16.f16.f32 "
        "{%0,%1,%2,%3}, {%4,%5,%6,%7}, {%8,%9}, {%0,%1,%2,%3};"
        : "+f"(c[0]), "+f"(c[1]), "+f"(c[2]), "+f"(c[3])
        : "r"(a0), "r"(a1), "r"(a2), "r"(a3), "r"(b0), "r"(b1));
}

__device__ __forceinline__ void ldsm_x4(unsigned r[4], uint32_t addr) {
    asm volatile("ldmatrix.sync.aligned.m8n8.x4.shared.b16 {%0,%1,%2,%3}, [%4];"
                 : "=r"(r[0]), "=r"(r[1]), "=r"(r[2]), "=r"(r[3]) : "r"(addr));
}

__device__ __forceinline__ uint32_t smem_u32(const void* p) {
    uint32_t a;
    asm("{ .reg .u64 t; cvta.to.shared.u64 t, %1; cvt.u32.u64 %0, t; }" : "=r"(a) : "l"(p));
    return a;
}

__device__ __forceinline__ float fast_silu(float v) {
    float t;
    asm("tanh.approx.f32 %0, %1;" : "=f"(t) : "f"(0.5f * v));
    return 0.5f * v * (t + 1.0f);
}
__device__ __forceinline__ unsigned packh2(float a, float b) {
    __half2 h = __floats2half2_rn(a, b);
    return *(unsigned*)&h;
}
__device__ __forceinline__ __half2 silu_h2(float c0, float c1, __half2 bias) {
    __half2 p = __hadd2(__floats2half2_rn(c0, c1), bias);
    __half2 u = __hmul2(p, __float2half2_rn(0.5f));
    __half2 t;
    asm("tanh.approx.f16x2 %0, %1;" : "=r"(*(unsigned*)&t) : "r"(*(unsigned*)&u));
    return __hfma2(u, t, u);
}

#define CP_ASYNC16(dst, src) \
    asm volatile("cp.async.cg.shared.global [%0], [%1], 16;" :: "r"(dst), "l"(src))
#define CP_COMMIT() asm volatile("cp.async.commit_group;" ::: "memory")
#define CP_WAIT0()  asm volatile("cp.async.wait_group 0;" ::: "memory")

// ---------------- transpose w[B,C,H,W] f32 -> wT[b][y][x][c] fp16 ----------------
__global__ void k_transpose(const float* __restrict__ w) {
    __shared__ float tile[64][65];
    int bid = blockIdx.x;
    int b = bid >> 6, y = bid & 63;
    int t = threadIdx.x;
    {
        int c = t >> 2, xq = (t & 3) * 16;
        const float4* src = (const float4*)(w + ((((b << 6) | c) << 6 | y) << 6) + xq);
#pragma unroll
        for (int j = 0; j < 4; j++) {
            float4 v = src[j];
            tile[c][xq + 4 * j + 0] = v.x;
            tile[c][xq + 4 * j + 1] = v.y;
            tile[c][xq + 4 * j + 2] = v.z;
            tile[c][xq + 4 * j + 3] = v.w;
        }
    }
    __syncthreads();
    {
        int xx = t >> 2, cq = (t & 3) * 16;
        __half2* dst = (__half2*)(g_wT + ((((size_t)(((b << 6) | y)) << 6 | xx)) << 6) + cq);
#pragma unroll
        for (int j = 0; j < 8; j++)
            dst[j] = __floats2half2_rn(tile[cq + 2 * j][xx], tile[cq + 2 * j + 1][xx]);
    }
}

// ---------------- pack weights (permuted cols: [lf 0..63 | cond 64..79 | z 80 | 0]) ----------------
__global__ void k_pack(const float* __restrict__ W0, const float* __restrict__ b0,
                       const float* __restrict__ W1, const float* __restrict__ b1) {
    int idx = blockIdx.x * 256 + threadIdx.x;
    int net = idx >> 16;
    int rem = idx & 65535;
    int layer = rem >> 14;
    int rem2 = rem & 16383;
    int n = rem2 >> 7, k = rem2 & 127;
    float v = 0.f;
    if (layer == 0) {
        int oc = -1;
        if (k < 64) oc = 1 + k;
        else if (k < 80) oc = 65 + (k - 64);
        else if (k == 80) oc = 0;
        if (oc >= 0) v = W0[(net * 128 + n) * 81 + oc];
    } else {
        v = W1[((net * 3 + (layer - 1)) * 128 + n) * 128 + k];
    }
    g_wts[idx] = __float2half_rn(v);
    if (idx < 2048) {
        int bn = idx >> 9, bl = (idx >> 7) & 3, bb_ = idx & 127;
        float bv = (bl == 0) ? b0[bn * 128 + bb_]
                             : b1[((bn * 3 + bl - 1) * 128) + bb_];
        g_biasH[idx] = __float2half_rn(bv);
    }
}

// ---------------- fused two-pass coupling kernel ----------------
__global__ void __launch_bounds__(NTHREADS, 2) k_fused(
    const float* __restrict__ x, const float* __restrict__ cond,
    const float* __restrict__ W2, const float* __restrict__ b2,
    float* __restrict__ out) {
    extern __shared__ __align__(16) char smraw[];
    __half* combS  = (__half*)(smraw + OFF_COMB);
    __half* hExS   = (__half*)(smraw + OFF_HEX);
    __half* sbiasH = (__half*)(smraw + OFF_BIAS);
    float*  w2s    = (float*)(smraw + OFF_W2);
    float*  spartS = (float*)(smraw + OFF_SPS);
    float*  spartT = (float*)(smraw + OFF_SPT);
    float*  zA     = (float*)(smraw + OFF_ZA);
    float*  sred   = (float*)(smraw + OFF_SRED);

    int tid = threadIdx.x;
    int wid = tid >> 5, lane = tid & 31;
    int gid = lane >> 2, tig = lane & 3;
    int rowg = wid & 3;          // 4 row-groups x 32 tokens = 128
    int colg = wid >> 2;         // 2 col-groups x 64 cols
    int tile = blockIdx.x;

    uint32_t combA = smem_u32(combS);
    uint32_t hExA  = smem_u32(hExS);
    uint32_t wbA   = smem_u32(smraw + OFF_WB);

    // prefetch layer 0 weights
#pragma unroll
    for (int i = 0; i < 8; i++) {
        int ci = tid + i * 256;
        int n = ci >> 4, q = ci & 15;
        CP_ASYNC16(wbA + (n * SH + q * 8) * 2, (const char*)g_wts + ci * 16);
    }
    CP_COMMIT();

    // stage biases (all 16 layers) + w2 (all 4 nets)
#pragma unroll
    for (int i = 0; i < 4; i++)
        ((unsigned*)sbiasH)[tid + i * 256] = ((const unsigned*)g_biasH)[tid + i * 256];
    w2s[tid] = __ldg(&W2[tid]);
    w2s[tid + 256] = __ldg(&W2[tid + 256]);

    // ldmatrix per-thread offsets
    int aRow = lane & 15;
    int aK   = (lane >> 4) * 8;
    int bRow = (lane & 7) + ((lane >> 4) & 1) * 8;
    int bK   = ((lane >> 3) & 1) * 8;

    unsigned aPack[2][8][2];

    for (int ps = 0; ps < 2; ps++) {
        // ===== gather + build comb (2 threads per token) =====
        {
            int tk = tid >> 1, p = tid & 1;
            int g0 = tile * TOKPC + tk;
            int b = g0 >> 12;
            float zy = __ldg(&x[g0 * 2 + 1]);
            float zx = (ps == 0) ? __ldg(&x[g0 * 2]) : zA[tk];
            float zkeep = (ps == 0) ? zy : zx;
            float ix = zx * 63.f, iy = zy * 63.f;
            float ix0 = floorf(ix), iy0 = floorf(iy);
            float wx1 = ix - ix0, wx0 = 1.f - wx1;
            float wy1 = iy - iy0, wy0 = 1.f - wy1;
            float acc[32];
#pragma unroll
            for (int i = 0; i < 32; i++) acc[i] = 0.f;
            float cxs[4] = {ix0, ix0 + 1.f, ix0, ix0 + 1.f};
            float cys[4] = {iy0, iy0, iy0 + 1.f, iy0 + 1.f};
            float cws[4] = {wy0 * wx0, wy0 * wx1, wy1 * wx0, wy1 * wx1};
#pragma unroll
            for (int cr = 0; cr < 4; cr++) {
                float xf = cxs[cr], yf = cys[cr], wt = cws[cr];
                if (xf >= 0.f && xf <= 63.f && yf >= 0.f && yf <= 63.f) {
                    int xi = (int)xf, yi = (int)yf;
                    const __half2* src = (const __half2*)(
                        g_wT + ((((size_t)((b << 6) | yi) << 6 | xi)) << 6) + (p << 5));
#pragma unroll
                    for (int j = 0; j < 16; j++) {
                        float2 f = __half22float2(src[j]);
                        acc[2 * j]     += wt * f.x;
                        acc[2 * j + 1] += wt * f.y;
                    }
                }
            }
            __half* crow = combS + tk * SC;
            __half2* dst = (__half2*)(crow + p * 32);
#pragma unroll
            for (int j = 0; j < 16; j++) dst[j] = __floats2half2_rn(acc[2 * j], acc[2 * j + 1]);
            if (p == 0) {
#pragma unroll
                for (int i = 0; i < 16; i++)
                    crow[64 + i] = __float2half_rn(__ldg(&cond[b * 16 + i]));
                crow[80] = __float2half_rn(zkeep);
#pragma unroll
                for (int cc = 81; cc < 88; cc++) crow[cc] = __float2half_rn(0.f);
            } else {
#pragma unroll
                for (int cc = 88; cc < 96; cc++) crow[cc] = __float2half_rn(0.f);
            }
        }
        CP_WAIT0();
        __syncthreads();   // comb + weights visible

        // ===== 8 layers of this pass =====
        for (int l = 0; l < 8; l++) {
            int li = ps * 8 + l;
            uint32_t bb = wbA + ((64 * colg + bRow) * SH + bK) * 2;

            float acc[2][8][4];
#pragma unroll
            for (int mt = 0; mt < 2; mt++)
#pragma unroll
                for (int nt = 0; nt < 8; nt++)
#pragma unroll
                    for (int q = 0; q < 4; q++) acc[mt][nt][q] = 0.f;

            if (l == 0 || l == 4) {
                // A from comb (K=96, 6 ksteps)
                uint32_t a0 = combA + ((32 * rowg + aRow) * SC + aK) * 2;
                uint32_t a1 = a0 + 16 * SC * 2;
#pragma unroll
                for (int ks = 0; ks < 6; ks++) {
                    unsigned af0[4], af1[4];
                    ldsm_x4(af0, a0 + ks * 32);
                    ldsm_x4(af1, a1 + ks * 32);
#pragma unroll
                    for (int ntp = 0; ntp < 4; ntp++) {
                        unsigned bf[4];
                        ldsm_x4(bf, bb + (ntp * 16 * SH) * 2 + ks * 32);
                        mma16816(acc[0][2 * ntp],     af0[0], af0[1], af0[2], af0[3], bf[0], bf[1]);
                        mma16816(acc[0][2 * ntp + 1], af0[0], af0[1], af0[2], af0[3], bf[2], bf[3]);
                        mma16816(acc[1][2 * ntp],     af1[0], af1[1], af1[2], af1[3], bf[0], bf[1]);
                        mma16816(acc[1][2 * ntp + 1], af1[0], af1[1], af1[2], af1[3], bf[2], bf[3]);
                    }
                }
            } else {
                // partner k-half from hEx (4 ksteps)
                int pc = colg ^ 1;
                uint32_t pbase = hExA + ((32 * rowg + aRow) * SHE + 64 * pc + aK) * 2;
                int pks0 = 4 * pc, oks0 = 4 * colg;
#pragma unroll
                for (int q = 0; q < 4; q++) {
                    unsigned af0[4], af1[4];
                    ldsm_x4(af0, pbase + q * 32);
                    ldsm_x4(af1, pbase + 16 * SHE * 2 + q * 32);
#pragma unroll
                    for (int ntp = 0; ntp < 4; ntp++) {
                        unsigned bf[4];
                        ldsm_x4(bf, bb + (ntp * 16 * SH) * 2 + (pks0 + q) * 32);
                        mma16816(acc[0][2 * ntp],     af0[0], af0[1], af0[2], af0[3], bf[0], bf[1]);
                        mma16816(acc[0][2 * ntp + 1], af0[0], af0[1], af0[2], af0[3], bf[2], bf[3]);
                        mma16816(acc[1][2 * ntp],     af1[0], af1[1], af1[2], af1[3], bf[0], bf[1]);
                        mma16816(acc[1][2 * ntp + 1], af1[0], af1[1], af1[2], af1[3], bf[2], bf[3]);
                    }
                }
                // own k-half from registers
#pragma unroll
                for (int q = 0; q < 4; q++) {
#pragma unroll
                    for (int ntp = 0; ntp < 4; ntp++) {
                        unsigned bf[4];
                        ldsm_x4(bf, bb + (ntp * 16 * SH) * 2 + (oks0 + q) * 32);
                        mma16816(acc[0][2 * ntp], aPack[0][2 * q][0], aPack[0][2 * q][1],
                                 aPack[0][2 * q + 1][0], aPack[0][2 * q + 1][1], bf[0], bf[1]);
                        mma16816(acc[0][2 * ntp + 1], aPack[0][2 * q][0], aPack[0][2 * q][1],
                                 aPack[0][2 * q + 1][0], aPack[0][2 * q + 1][1], bf[2], bf[3]);
                        mma16816(acc[1][2 * ntp], aPack[1][2 * q][0], aPack[1][2 * q][1],
                                 aPack[1][2 * q + 1][0], aPack[1][2 * q + 1][1], bf[0], bf[1]);
                        mma16816(acc[1][2 * ntp + 1], aPack[1][2 * q][0], aPack[1][2 * q][1],
                                 aPack[1][2 * q + 1][0], aPack[1][2 * q + 1][1], bf[2], bf[3]);
                    }
                }
            }

            __syncthreads();   // all MMA reads (wb/hEx/comb) done

            // prefetch next layer's weights into the (now free) single buffer
            if (li < 15) {
                const char* srcp = (const char*)g_wts + ((size_t)(li + 1) << 15);
#pragma unroll
                for (int i = 0; i < 8; i++) {
                    int ci = tid + i * 256;
                    int n = ci >> 4, q = ci & 15;
                    CP_ASYNC16(wbA + (n * SH + q * 8) * 2, srcp + ci * 16);
                }
                CP_COMMIT();
            }

            const __half* lbH = sbiasH + li * 128 + 64 * colg;
            if (l == 3 || l == 7) {
                // final GEMV of this net over our 64 cols
                float* sp = (l == 3) ? spartS : spartT;
                const float* w2 = w2s + (li >> 2) * 128 + 64 * colg;
#pragma unroll
                for (int mt = 0; mt < 2; mt++) {
                    float p0 = 0.f, p1 = 0.f;
                    if (l == 3) {
#pragma unroll
                        for (int nt = 0; nt < 8; nt++) {
                            int c = nt * 8 + tig * 2;
                            float2 bf2 = __half22float2(*(const __half2*)(lbH + c));
                            float w0 = w2[c], w1 = w2[c + 1];
                            p0 += fast_silu(acc[mt][nt][0] + bf2.x) * w0
                                + fast_silu(acc[mt][nt][1] + bf2.y) * w1;
                            p1 += fast_silu(acc[mt][nt][2] + bf2.x) * w0
                                + fast_silu(acc[mt][nt][3] + bf2.y) * w1;
                        }
                    } else {
#pragma unroll
                        for (int nt = 0; nt < 8; nt++) {
                            int c = nt * 8 + tig * 2;
                            __half2 bias = *(const __half2*)(lbH + c);
                            float w0 = w2[c], w1 = w2[c + 1];
                            float2 f0 = __half22float2(silu_h2(acc[mt][nt][0], acc[mt][nt][1], bias));
                            float2 f1 = __half22float2(silu_h2(acc[mt][nt][2], acc[mt][nt][3], bias));
                            p0 += f0.x * w0 + f0.y * w1;
                            p1 += f1.x * w0 + f1.y * w1;
                        }
                    }
                    p0 += __shfl_xor_sync(0xffffffffu, p0, 1);
                    p0 += __shfl_xor_sync(0xffffffffu, p0, 2);
                    p1 += __shfl_xor_sync(0xffffffffu, p1, 1);
                    p1 += __shfl_xor_sync(0xffffffffu, p1, 2);
                    if (tig == 0) {
                        sp[colg * 128 + 32 * rowg + 16 * mt + gid]     = p0;
                        sp[colg * 128 + 32 * rowg + 16 * mt + gid + 8] = p1;
                    }
                }
            } else {
                // interior epilogue: silu -> aPack (own half) + hEx (for partner)
#pragma unroll
                for (int mt = 0; mt < 2; mt++) {
                    __half* exb = hExS + (32 * rowg + 16 * mt + gid) * SHE + 64 * colg + tig * 2;
#pragma unroll
                    for (int nt = 0; nt < 8; nt++) {
                        unsigned r0, r1;
                        if (l < 3) {
                            float2 bf2 = __half22float2(*(const __half2*)(lbH + nt * 8 + tig * 2));
                            r0 = packh2(fast_silu(acc[mt][nt][0] + bf2.x),
                                        fast_silu(acc[mt][nt][1] + bf2.y));
                            r1 = packh2(fast_silu(acc[mt][nt][2] + bf2.x),
                                        fast_silu(acc[mt][nt][3] + bf2.y));
                        } else {
                            __half2 bias = *(const __half2*)(lbH + nt * 8 + tig * 2);
                            __half2 h0 = silu_h2(acc[mt][nt][0], acc[mt][nt][1], bias);
                            __half2 h1 = silu_h2(acc[mt][nt][2], acc[mt][nt][3], bias);
                            r0 = *(unsigned*)&h0;
                            r1 = *(unsigned*)&h1;
                        }
                        aPack[mt][nt][0] = r0;
                        aPack[mt][nt][1] = r1;
                        *(unsigned*)(exb + nt * 8)           = r0;
                        *(unsigned*)(exb + 8 * SHE + nt * 8) = r1;
                    }
                }
            }

            CP_WAIT0();
            __syncthreads();   // next weights ready + hEx writes visible
        }

        // ===== coupling epilogue for this pass =====
        if (tid < TOKPC) {
            int g0 = tile * TOKPC + tid;
            float zold = (ps == 0) ? __ldg(&x[g0 * 2]) : __ldg(&x[g0 * 2 + 1]);
            float s_lin = spartS[tid] + spartS[128 + tid] + __ldg(&b2[ps * 2]);
            float t_lin = spartT[tid] + spartT[128 + tid] + __ldg(&b2[ps * 2 + 1]);
            float sv = tanhf(s_lin) * 1.5f;
            float z = zold * __expf(sv) + t_lin;
            out[g0 * 2 + ps] = z;
            if (ps == 0) { zA[tid] = z; sred[tid] = sv; }
            else sred[tid] += sv;
        }
        __syncthreads();
    }

    // ===== deterministic block reduce of s (both passes) =====
    if (tid < 64) sred[tid] += sred[tid + 64];
    __syncthreads();
    if (tid < 32) {
        float v = sred[tid] + sred[tid + 32];
#pragma unroll
        for (int off = 16; off; off >>= 1) v += __shfl_xor_sync(0xffffffffu, v, off);
        if (tid == 0) g_part[tile] = v;
    }
}

// ---------------- log-det reduce ----------------
__global__ void k_reduce(float* __restrict__ out) {
    int b = threadIdx.x;
    if (b < BB) {
        float acc = 0.f;
        for (int i = 0; i < 32; i++)
            acc += g_part[b * 32 + i];
        out[(size_t)NTOK * 2 + b] = acc;
    }
}

// ---------------- launcher ----------------
extern "C" void kernel_launch(void* const* d_in, const int* in_sizes, int n_in,
                              void* d_out, int out_size) {
    const float* x    = (const float*)d_in[0];
    const float* w    = (const float*)d_in[1];
    const float* cond = (const float*)d_in[2];
    const float* W0   = (const float*)d_in[3];
    const float* b0   = (const float*)d_in[4];
    const float* W1   = (const float*)d_in[5];
    const float* b1   = (const float*)d_in[6];
    const float* W2   = (const float*)d_in[7];
    const float* b2   = (const float*)d_in[8];
    float* out = (float*)d_out;

    cudaFuncSetAttribute(k_fused, cudaFuncAttributeMaxDynamicSharedMemorySize, SMEM_TOT);

    k_transpose<<<4096, 256>>>(w);
    k_pack<<<1024, 256>>>(W0, b0, W1, b1);
    k_fused<<<NCTAS, NTHREADS, SMEM_TOT>>>(x, cond, W2, b2, out);
    k_reduce<<<1, 64>>>(out);
}